// round 1
// baseline (speedup 1.0000x reference)
#include <cuda_runtime.h>
#include <cstdint>
#include <math_constants.h>

// Problem constants (fixed by the dataset)
#define MAXN 100000
#define IN_DIM 128
#define HID 512
#define NCLS 40

// Scratch (allocation-free: __device__ globals)
__device__ float g_deg [MAXN];
__device__ float g_dinv[MAXN];
__device__ float g_ax  [(size_t)MAXN * IN_DIM];   //  51.2 MB  agg(x)
__device__ float g_h1  [(size_t)MAXN * HID];      // 204.8 MB  relu(agg(x)W1+b1)
__device__ float g_g2  [(size_t)MAXN * NCLS];     //  16.0 MB  h1 W2
__device__ float g_oagg[(size_t)MAXN * NCLS];     //  16.0 MB  agg(g2)

// ---------------------------------------------------------------------------
__global__ void k_init_deg(int N) {
    int i = blockIdx.x * blockDim.x + threadIdx.x;
    if (i < N) g_deg[i] = 1.0f;   // self-loop
}

__global__ void k_zero(float* p, size_t n) {
    size_t i = (size_t)blockIdx.x * blockDim.x + threadIdx.x;
    size_t stride = (size_t)gridDim.x * blockDim.x;
    for (; i < n; i += stride) p[i] = 0.0f;
}

__global__ void k_deg(const int* __restrict__ dst, int E) {
    int e = blockIdx.x * blockDim.x + threadIdx.x;
    if (e < E) atomicAdd(&g_deg[dst[e]], 1.0f);
}

__global__ void k_dinv(int N) {
    int i = blockIdx.x * blockDim.x + threadIdx.x;
    if (i < N) g_dinv[i] = rsqrtf(g_deg[i]);
}

// ---------------------------------------------------------------------------
// Aggregate x (128-wide): one warp per unit (edge or self-loop).
// g_ax[d] += norm * x[s]
__global__ void k_aggx(const float* __restrict__ x, const int* __restrict__ src,
                       const int* __restrict__ dst, int E, int U) {
    int u = (int)((blockIdx.x * (unsigned)blockDim.x + threadIdx.x) >> 5);
    int l = threadIdx.x & 31;
    if (u >= U) return;
    int s, d;
    if (u < E) { s = src[u]; d = dst[u]; }
    else       { s = d = u - E; }
    float nrm = g_dinv[s] * g_dinv[d];
    float4 v = *(const float4*)(x + (size_t)s * IN_DIM + l * 4);
    float* p = g_ax + (size_t)d * IN_DIM + l * 4;
    asm volatile("red.global.add.v4.f32 [%0], {%1,%2,%3,%4};"
                 :: "l"(p), "f"(v.x * nrm), "f"(v.y * nrm),
                    "f"(v.z * nrm), "f"(v.w * nrm) : "memory");
}

// ---------------------------------------------------------------------------
// GEMM1: h1 = relu(g_ax[N,128] @ W1[128,512] + b1), fp32 SIMT, 64x64 tiles, BK=64
__global__ void __launch_bounds__(256) k_gemm1(const float* __restrict__ W1,
                                               const float* __restrict__ b1, int N) {
    __shared__ float As[64][68];   // [row][k], padded (68*4B row = 17*16B)
    __shared__ float Bs[64][64];   // [k][col]
    int bx = blockIdx.x;           // col block: 0..7
    int by = blockIdx.y;           // row block
    int t  = threadIdx.x;
    int row0 = by * 64;
    int tx = t & 15, ty = t >> 4;  // 16x16 thread grid, 4x4 micro-tile
    float acc[4][4] = {};

    for (int kc = 0; kc < 2; kc++) {
        // load A chunk: 64 rows x 64 cols = 1024 float4, 4 per thread
        #pragma unroll
        for (int i = 0; i < 4; i++) {
            int f  = t + i * 256;
            int r  = f >> 4;          // 0..63
            int c4 = f & 15;          // 0..15
            int gr = row0 + r;
            float4 v = make_float4(0.f, 0.f, 0.f, 0.f);
            if (gr < N) v = *(const float4*)(g_ax + (size_t)gr * IN_DIM + kc * 64 + c4 * 4);
            *(float4*)&As[r][c4 * 4] = v;
        }
        // load B chunk: 64 k x 64 cols = 1024 float4, 4 per thread
        #pragma unroll
        for (int i = 0; i < 4; i++) {
            int f  = t + i * 256;
            int k  = f >> 4;
            int c4 = f & 15;
            float4 v = *(const float4*)(W1 + (size_t)(kc * 64 + k) * HID + bx * 64 + c4 * 4);
            *(float4*)&Bs[k][c4 * 4] = v;
        }
        __syncthreads();
        #pragma unroll 16
        for (int k = 0; k < 64; k++) {
            float a0 = As[ty * 4 + 0][k];
            float a1 = As[ty * 4 + 1][k];
            float a2 = As[ty * 4 + 2][k];
            float a3 = As[ty * 4 + 3][k];
            float4 b = *(float4*)&Bs[k][tx * 4];
            acc[0][0] += a0 * b.x; acc[0][1] += a0 * b.y; acc[0][2] += a0 * b.z; acc[0][3] += a0 * b.w;
            acc[1][0] += a1 * b.x; acc[1][1] += a1 * b.y; acc[1][2] += a1 * b.z; acc[1][3] += a1 * b.w;
            acc[2][0] += a2 * b.x; acc[2][1] += a2 * b.y; acc[2][2] += a2 * b.z; acc[2][3] += a2 * b.w;
            acc[3][0] += a3 * b.x; acc[3][1] += a3 * b.y; acc[3][2] += a3 * b.z; acc[3][3] += a3 * b.w;
        }
        __syncthreads();
    }

    int cbase = bx * 64 + tx * 4;
    float4 bias = *(const float4*)(b1 + cbase);
    #pragma unroll
    for (int i = 0; i < 4; i++) {
        int gr = row0 + ty * 4 + i;
        if (gr >= N) continue;
        float4 o;
        o.x = fmaxf(acc[i][0] + bias.x, 0.f);
        o.y = fmaxf(acc[i][1] + bias.y, 0.f);
        o.z = fmaxf(acc[i][2] + bias.z, 0.f);
        o.w = fmaxf(acc[i][3] + bias.w, 0.f);
        *(float4*)(g_h1 + (size_t)gr * HID + cbase) = o;
    }
}

// ---------------------------------------------------------------------------
// GEMM2: g2 = h1[N,512] @ W2[512,40]. 32 rows per block, 256 threads,
// thread = (row, 5-col group). K staged in 128-chunks.
__global__ void __launch_bounds__(256) k_gemm2(const float* __restrict__ W2, int N) {
    __shared__ float As[32][132];   // padded: bank = (4r + k) % 32
    __shared__ float Ws[128][NCLS];
    int by = blockIdx.x;
    int t  = threadIdx.x;
    int row0 = by * 32;
    int tr = t >> 3;            // 0..31
    int tc = (t & 7) * 5;       // 0,5,...,35
    float acc[5] = {};

    for (int kc = 0; kc < 4; kc++) {
        #pragma unroll
        for (int i = 0; i < 4; i++) {
            int f  = t + i * 256;          // 0..1023
            int r  = f >> 5;               // 0..31
            int c4 = f & 31;               // 0..31
            int gr = row0 + r;
            float4 v = make_float4(0.f, 0.f, 0.f, 0.f);
            if (gr < N) v = *(const float4*)(g_h1 + (size_t)gr * HID + kc * 128 + c4 * 4);
            *(float4*)&As[r][c4 * 4] = v;
        }
        #pragma unroll
        for (int i = 0; i < 20; i++) {
            int f = t + i * 256;           // 0..5119
            int k = f / NCLS;
            int c = f % NCLS;
            Ws[k][c] = W2[(size_t)(kc * 128 + k) * NCLS + c];
        }
        __syncthreads();
        #pragma unroll 8
        for (int k = 0; k < 128; k++) {
            float a = As[tr][k];
            #pragma unroll
            for (int j = 0; j < 5; j++) acc[j] += a * Ws[k][tc + j];
        }
        __syncthreads();
    }
    int gr = row0 + tr;
    if (gr < N) {
        #pragma unroll
        for (int j = 0; j < 5; j++) g_g2[(size_t)gr * NCLS + tc + j] = acc[j];
    }
}

// ---------------------------------------------------------------------------
// Aggregate g2 (40-wide): 10 float4 per unit, one thread per (unit, quad)
__global__ void k_aggg(const int* __restrict__ src, const int* __restrict__ dst,
                       int E, int U) {
    long gt = (long)blockIdx.x * blockDim.x + threadIdx.x;
    int u = (int)(gt / 10);
    int q = (int)(gt % 10);
    if (u >= U) return;
    int s, d;
    if (u < E) { s = src[u]; d = dst[u]; }
    else       { s = d = u - E; }
    float nrm = g_dinv[s] * g_dinv[d];
    float4 v = *(const float4*)(g_g2 + (size_t)s * NCLS + q * 4);
    float* p = g_oagg + (size_t)d * NCLS + q * 4;
    asm volatile("red.global.add.v4.f32 [%0], {%1,%2,%3,%4};"
                 :: "l"(p), "f"(v.x * nrm), "f"(v.y * nrm),
                    "f"(v.z * nrm), "f"(v.w * nrm) : "memory");
}

// ---------------------------------------------------------------------------
// out = log_softmax(g_oagg + b2) per row. One warp per row; lane l covers
// col l, and col 32+l for l<8.
__global__ void k_lsm(const float* __restrict__ b2, float* __restrict__ out, int N) {
    int w = (int)((blockIdx.x * (unsigned)blockDim.x + threadIdx.x) >> 5);
    int l = threadIdx.x & 31;
    if (w >= N) return;
    const float* row = g_oagg + (size_t)w * NCLS;
    float v0 = row[l] + b2[l];
    float v1 = (l < 8) ? (row[32 + l] + b2[32 + l]) : -CUDART_INF_F;
    float m = fmaxf(v0, v1);
    #pragma unroll
    for (int o = 16; o; o >>= 1) m = fmaxf(m, __shfl_xor_sync(0xffffffffu, m, o));
    float s = expf(v0 - m) + ((l < 8) ? expf(v1 - m) : 0.f);
    #pragma unroll
    for (int o = 16; o; o >>= 1) s += __shfl_xor_sync(0xffffffffu, s, o);
    float lse = m + logf(s);
    out[(size_t)w * NCLS + l] = v0 - lse;
    if (l < 8) out[(size_t)w * NCLS + 32 + l] = v1 - lse;
}

// ---------------------------------------------------------------------------
extern "C" void kernel_launch(void* const* d_in, const int* in_sizes, int n_in,
                              void* d_out, int out_size) {
    const float* x  = (const float*)d_in[0];
    const int*   ei = (const int*)  d_in[1];
    const float* W1 = (const float*)d_in[2];
    const float* b1 = (const float*)d_in[3];
    const float* W2 = (const float*)d_in[4];
    const float* b2 = (const float*)d_in[5];
    float* out = (float*)d_out;

    int N = in_sizes[0] / IN_DIM;     // 100000
    int E = in_sizes[1] / 2;          // 500000
    const int* src = ei;
    const int* dst = ei + E;
    int U = E + N;

    float *p_ax, *p_oagg;
    cudaGetSymbolAddress((void**)&p_ax,   g_ax);
    cudaGetSymbolAddress((void**)&p_oagg, g_oagg);

    (void)b1; // used in gemm1

    k_init_deg<<<(N + 255) / 256, 256>>>(N);
    k_zero<<<2048, 256>>>(p_ax,   (size_t)N * IN_DIM);
    k_zero<<<1024, 256>>>(p_oagg, (size_t)N * NCLS);
    k_deg <<<(E + 255) / 256, 256>>>(dst, E);
    k_dinv<<<(N + 255) / 256, 256>>>(N);

    // aggregate x: one warp per unit
    {
        long threads = (long)U * 32;
        int blocks = (int)((threads + 255) / 256);
        k_aggx<<<blocks, 256>>>(x, src, dst, E, U);
    }

    // GEMM1 + bias + relu
    {
        dim3 grid(HID / 64, (N + 63) / 64);
        k_gemm1<<<grid, 256>>>(W1, b1, N);
    }

    // GEMM2
    k_gemm2<<<(N + 31) / 32, 256>>>(W2, N);

    // aggregate g2
    {
        long threads = (long)U * 10;
        int blocks = (int)((threads + 255) / 256);
        k_aggg<<<blocks, 256>>>(src, dst, E, U);
    }

    // bias + log_softmax -> d_out
    {
        long threads = (long)N * 32;
        int blocks = (int)((threads + 255) / 256);
        k_lsm<<<blocks, 256>>>(b2, out, N);
    }
}

// round 2
// speedup vs baseline: 1.3382x; 1.3382x over previous
#include <cuda_runtime.h>
#include <cstdint>
#include <math_constants.h>

#define MAXN 100000
#define IN_DIM 128
#define HID 512
#define NCLS 40

__device__ float g_deg [MAXN];
__device__ float g_dinv[MAXN];
__device__ float g_ax  [(size_t)MAXN * IN_DIM];
__device__ float g_h1  [(size_t)MAXN * HID];
__device__ float g_g2  [(size_t)MAXN * NCLS];
__device__ float g_oagg[(size_t)MAXN * NCLS];

// ---------------------------------------------------------------------------
__global__ void k_init_deg(int N) {
    int i = blockIdx.x * blockDim.x + threadIdx.x;
    if (i < N) g_deg[i] = 1.0f;
}

__global__ void k_zero(float* p, size_t n) {
    size_t i = (size_t)blockIdx.x * blockDim.x + threadIdx.x;
    size_t stride = (size_t)gridDim.x * blockDim.x;
    for (; i < n; i += stride) p[i] = 0.0f;
}

__global__ void k_deg(const int* __restrict__ dst, int E) {
    int e = blockIdx.x * blockDim.x + threadIdx.x;
    if (e < E) atomicAdd(&g_deg[dst[e]], 1.0f);
}

__global__ void k_dinv(int N) {
    int i = blockIdx.x * blockDim.x + threadIdx.x;
    if (i < N) g_dinv[i] = rsqrtf(g_deg[i]);
}

// ---------------------------------------------------------------------------
__global__ void k_aggx(const float* __restrict__ x, const int* __restrict__ src,
                       const int* __restrict__ dst, int E, int U) {
    int u = (int)((blockIdx.x * (unsigned)blockDim.x + threadIdx.x) >> 5);
    int l = threadIdx.x & 31;
    if (u >= U) return;
    int s, d;
    if (u < E) { s = src[u]; d = dst[u]; }
    else       { s = d = u - E; }
    float nrm = g_dinv[s] * g_dinv[d];
    float4 v = *(const float4*)(x + (size_t)s * IN_DIM + l * 4);
    float* p = g_ax + (size_t)d * IN_DIM + l * 4;
    asm volatile("red.global.add.v4.f32 [%0], {%1,%2,%3,%4};"
                 :: "l"(p), "f"(v.x * nrm), "f"(v.y * nrm),
                    "f"(v.z * nrm), "f"(v.w * nrm) : "memory");
}

// ---------------------------------------------------------------------------
// GEMM1 on tensor pipe: h1 = relu(g_ax[N,128] @tf32 W1[128,512] + b1)
// 128x128 block tile, 8 warps (32x64 each), K chunked by 32.
__device__ __forceinline__ uint32_t f2tf32(float v) {
    uint32_t o;
    asm("cvt.rna.tf32.f32 %0, %1;" : "=r"(o) : "f"(v));
    return o;
}

__global__ void __launch_bounds__(256) k_gemm1_tc(const float* __restrict__ W1,
                                                  const float* __restrict__ b1, int N) {
    __shared__ float As[128][36];   // [m][k], (4g+t)%32 distinct -> conflict-free frags
    __shared__ float Bs[32][132];   // [k][n]
    const int t    = threadIdx.x;
    const int wid  = t >> 5;
    const int lane = t & 31;
    const int g    = lane >> 2;     // group 0..7
    const int tg   = lane & 3;      // thread-in-group 0..3
    const int wm   = wid & 3;       // warp row  (4 x 32 rows)
    const int wn   = wid >> 2;      // warp col  (2 x 64 cols)
    const int row0 = blockIdx.y * 128;
    const int col0 = blockIdx.x * 128;

    float acc[2][8][4];
    #pragma unroll
    for (int a = 0; a < 2; a++)
        #pragma unroll
        for (int b = 0; b < 8; b++)
            #pragma unroll
            for (int c = 0; c < 4; c++) acc[a][b][c] = 0.f;

    for (int kc = 0; kc < 4; kc++) {
        // A: 128 rows x 32 k  (1024 float4)
        #pragma unroll
        for (int i = 0; i < 4; i++) {
            int f  = t + i * 256;
            int r  = f >> 3;
            int c4 = f & 7;
            int gr = row0 + r;
            float4 v = make_float4(0.f, 0.f, 0.f, 0.f);
            if (gr < N) v = *(const float4*)(g_ax + (size_t)gr * IN_DIM + kc * 32 + c4 * 4);
            float* p = &As[r][c4 * 4];
            p[0] = __uint_as_float(f2tf32(v.x));
            p[1] = __uint_as_float(f2tf32(v.y));
            p[2] = __uint_as_float(f2tf32(v.z));
            p[3] = __uint_as_float(f2tf32(v.w));
        }
        // B: 32 k x 128 cols (1024 float4)
        #pragma unroll
        for (int i = 0; i < 4; i++) {
            int f  = t + i * 256;
            int k  = f >> 5;
            int c4 = f & 31;
            float4 v = *(const float4*)(W1 + (size_t)(kc * 32 + k) * HID + col0 + c4 * 4);
            float* p = &Bs[k][c4 * 4];
            p[0] = __uint_as_float(f2tf32(v.x));
            p[1] = __uint_as_float(f2tf32(v.y));
            p[2] = __uint_as_float(f2tf32(v.z));
            p[3] = __uint_as_float(f2tf32(v.w));
        }
        __syncthreads();

        #pragma unroll
        for (int ks = 0; ks < 4; ks++) {
            const int k0 = ks * 8;
            uint32_t af[2][4];
            #pragma unroll
            for (int mi = 0; mi < 2; mi++) {
                int mb = wm * 32 + mi * 16;
                af[mi][0] = __float_as_uint(As[mb + g    ][k0 + tg    ]);
                af[mi][1] = __float_as_uint(As[mb + g + 8][k0 + tg    ]);
                af[mi][2] = __float_as_uint(As[mb + g    ][k0 + tg + 4]);
                af[mi][3] = __float_as_uint(As[mb + g + 8][k0 + tg + 4]);
            }
            uint32_t bf[8][2];
            #pragma unroll
            for (int ni = 0; ni < 8; ni++) {
                int nb = wn * 64 + ni * 8 + g;
                bf[ni][0] = __float_as_uint(Bs[k0 + tg    ][nb]);
                bf[ni][1] = __float_as_uint(Bs[k0 + tg + 4][nb]);
            }
            #pragma unroll
            for (int mi = 0; mi < 2; mi++)
                #pragma unroll
                for (int ni = 0; ni < 8; ni++) {
                    float* d = acc[mi][ni];
                    asm volatile(
                        "mma.sync.aligned.m16n8k8.row.col.f32.tf32.tf32.f32 "
                        "{%0,%1,%2,%3}, {%4,%5,%6,%7}, {%8,%9}, {%0,%1,%2,%3};"
                        : "+f"(d[0]), "+f"(d[1]), "+f"(d[2]), "+f"(d[3])
                        : "r"(af[mi][0]), "r"(af[mi][1]), "r"(af[mi][2]), "r"(af[mi][3]),
                          "r"(bf[ni][0]), "r"(bf[ni][1]));
                }
        }
        __syncthreads();
    }

    // epilogue: bias + relu, write h1
    const int cb = col0 + wn * 64;
    #pragma unroll
    for (int ni = 0; ni < 8; ni++) {
        int c = cb + ni * 8 + tg * 2;
        float2 bias = *(const float2*)(b1 + c);
        #pragma unroll
        for (int mi = 0; mi < 2; mi++) {
            int r0 = row0 + wm * 32 + mi * 16 + g;
            if (r0 < N) {
                float2 o;
                o.x = fmaxf(acc[mi][ni][0] + bias.x, 0.f);
                o.y = fmaxf(acc[mi][ni][1] + bias.y, 0.f);
                *(float2*)(g_h1 + (size_t)r0 * HID + c) = o;
            }
            int r1 = r0 + 8;
            if (r1 < N) {
                float2 o;
                o.x = fmaxf(acc[mi][ni][2] + bias.x, 0.f);
                o.y = fmaxf(acc[mi][ni][3] + bias.y, 0.f);
                *(float2*)(g_h1 + (size_t)r1 * HID + c) = o;
            }
        }
    }
}

// ---------------------------------------------------------------------------
__global__ void __launch_bounds__(256) k_gemm2(const float* __restrict__ W2, int N) {
    __shared__ float As[32][132];
    __shared__ float Ws[128][NCLS];
    int by = blockIdx.x;
    int t  = threadIdx.x;
    int row0 = by * 32;
    int tr = t >> 3;
    int tc = (t & 7) * 5;
    float acc[5] = {};

    for (int kc = 0; kc < 4; kc++) {
        #pragma unroll
        for (int i = 0; i < 4; i++) {
            int f  = t + i * 256;
            int r  = f >> 5;
            int c4 = f & 31;
            int gr = row0 + r;
            float4 v = make_float4(0.f, 0.f, 0.f, 0.f);
            if (gr < N) v = *(const float4*)(g_h1 + (size_t)gr * HID + kc * 128 + c4 * 4);
            *(float4*)&As[r][c4 * 4] = v;
        }
        #pragma unroll
        for (int i = 0; i < 20; i++) {
            int f = t + i * 256;
            int k = f / NCLS;
            int c = f % NCLS;
            Ws[k][c] = W2[(size_t)(kc * 128 + k) * NCLS + c];
        }
        __syncthreads();
        #pragma unroll 8
        for (int k = 0; k < 128; k++) {
            float a = As[tr][k];
            #pragma unroll
            for (int j = 0; j < 5; j++) acc[j] += a * Ws[k][tc + j];
        }
        __syncthreads();
    }
    int gr = row0 + tr;
    if (gr < N) {
        #pragma unroll
        for (int j = 0; j < 5; j++) g_g2[(size_t)gr * NCLS + tc + j] = acc[j];
    }
}

// ---------------------------------------------------------------------------
__global__ void k_aggg(const int* __restrict__ src, const int* __restrict__ dst,
                       int E, int U) {
    long gt = (long)blockIdx.x * blockDim.x + threadIdx.x;
    int u = (int)(gt / 10);
    int q = (int)(gt % 10);
    if (u >= U) return;
    int s, d;
    if (u < E) { s = src[u]; d = dst[u]; }
    else       { s = d = u - E; }
    float nrm = g_dinv[s] * g_dinv[d];
    float4 v = *(const float4*)(g_g2 + (size_t)s * NCLS + q * 4);
    float* p = g_oagg + (size_t)d * NCLS + q * 4;
    asm volatile("red.global.add.v4.f32 [%0], {%1,%2,%3,%4};"
                 :: "l"(p), "f"(v.x * nrm), "f"(v.y * nrm),
                    "f"(v.z * nrm), "f"(v.w * nrm) : "memory");
}

// ---------------------------------------------------------------------------
__global__ void k_lsm(const float* __restrict__ b2, float* __restrict__ out, int N) {
    int w = (int)((blockIdx.x * (unsigned)blockDim.x + threadIdx.x) >> 5);
    int l = threadIdx.x & 31;
    if (w >= N) return;
    const float* row = g_oagg + (size_t)w * NCLS;
    float v0 = row[l] + b2[l];
    float v1 = (l < 8) ? (row[32 + l] + b2[32 + l]) : -CUDART_INF_F;
    float m = fmaxf(v0, v1);
    #pragma unroll
    for (int o = 16; o; o >>= 1) m = fmaxf(m, __shfl_xor_sync(0xffffffffu, m, o));
    float s = expf(v0 - m) + ((l < 8) ? expf(v1 - m) : 0.f);
    #pragma unroll
    for (int o = 16; o; o >>= 1) s += __shfl_xor_sync(0xffffffffu, s, o);
    float lse = m + logf(s);
    out[(size_t)w * NCLS + l] = v0 - lse;
    if (l < 8) out[(size_t)w * NCLS + 32 + l] = v1 - lse;
}

// ---------------------------------------------------------------------------
extern "C" void kernel_launch(void* const* d_in, const int* in_sizes, int n_in,
                              void* d_out, int out_size) {
    const float* x  = (const float*)d_in[0];
    const int*   ei = (const int*)  d_in[1];
    const float* W1 = (const float*)d_in[2];
    const float* b1 = (const float*)d_in[3];
    const float* W2 = (const float*)d_in[4];
    const float* b2 = (const float*)d_in[5];
    float* out = (float*)d_out;

    int N = in_sizes[0] / IN_DIM;
    int E = in_sizes[1] / 2;
    const int* src = ei;
    const int* dst = ei + E;
    int U = E + N;

    float *p_ax, *p_oagg;
    cudaGetSymbolAddress((void**)&p_ax,   g_ax);
    cudaGetSymbolAddress((void**)&p_oagg, g_oagg);

    k_init_deg<<<(N + 255) / 256, 256>>>(N);
    k_zero<<<2048, 256>>>(p_ax,   (size_t)N * IN_DIM);
    k_zero<<<1024, 256>>>(p_oagg, (size_t)N * NCLS);
    k_deg <<<(E + 255) / 256, 256>>>(dst, E);
    k_dinv<<<(N + 255) / 256, 256>>>(N);

    {
        long threads = (long)U * 32;
        int blocks = (int)((threads + 255) / 256);
        k_aggx<<<blocks, 256>>>(x, src, dst, E, U);
    }

    {
        dim3 grid(HID / 128, (N + 127) / 128);
        k_gemm1_tc<<<grid, 256>>>(W1, b1, N);
    }

    k_gemm2<<<(N + 31) / 32, 256>>>(W2, N);

    {
        long threads = (long)U * 10;
        int blocks = (int)((threads + 255) / 256);
        k_aggg<<<blocks, 256>>>(src, dst, E, U);
    }

    {
        long threads = (long)N * 32;
        int blocks = (int)((threads + 255) / 256);
        k_lsm<<<blocks, 256>>>(b2, out, N);
    }
}

// round 3
// speedup vs baseline: 2.4323x; 1.8176x over previous
#include <cuda_runtime.h>
#include <cstdint>
#include <math_constants.h>

#define MAXN 100000
#define IN_DIM 128
#define HID 512
#define NCLS 40

__device__ float g_deg [MAXN];
__device__ float g_dinv[MAXN];
__device__ float g_ax  [(size_t)MAXN * IN_DIM];
__device__ float g_g2  [(size_t)MAXN * NCLS];
__device__ float g_oagg[(size_t)MAXN * NCLS];

// ---------------------------------------------------------------------------
__global__ void k_init_deg(int N) {
    int i = blockIdx.x * blockDim.x + threadIdx.x;
    if (i < N) g_deg[i] = 1.0f;
}

__global__ void k_zero(float* p, size_t n) {
    size_t i = (size_t)blockIdx.x * blockDim.x + threadIdx.x;
    size_t stride = (size_t)gridDim.x * blockDim.x;
    for (; i < n; i += stride) p[i] = 0.0f;
}

__global__ void k_deg(const int* __restrict__ dst, int E) {
    int e = blockIdx.x * blockDim.x + threadIdx.x;
    if (e < E) atomicAdd(&g_deg[dst[e]], 1.0f);
}

__global__ void k_dinv(int N) {
    int i = blockIdx.x * blockDim.x + threadIdx.x;
    if (i < N) g_dinv[i] = rsqrtf(g_deg[i]);
}

// ---------------------------------------------------------------------------
__global__ void k_aggx(const float* __restrict__ x, const int* __restrict__ src,
                       const int* __restrict__ dst, int E, int U) {
    int u = (int)((blockIdx.x * (unsigned)blockDim.x + threadIdx.x) >> 5);
    int l = threadIdx.x & 31;
    if (u >= U) return;
    int s, d;
    if (u < E) { s = src[u]; d = dst[u]; }
    else       { s = d = u - E; }
    float nrm = g_dinv[s] * g_dinv[d];
    float4 v = *(const float4*)(x + (size_t)s * IN_DIM + l * 4);
    float* p = g_ax + (size_t)d * IN_DIM + l * 4;
    asm volatile("red.global.add.v4.f32 [%0], {%1,%2,%3,%4};"
                 :: "l"(p), "f"(v.x * nrm), "f"(v.y * nrm),
                    "f"(v.z * nrm), "f"(v.w * nrm) : "memory");
}

// ---------------------------------------------------------------------------
__device__ __forceinline__ uint32_t f2tf32(float v) {
    uint32_t o;
    asm("cvt.rna.tf32.f32 %0, %1;" : "=r"(o) : "f"(v));
    return o;
}

// Fused: g2 = relu(Ax @ W1 + b1) @ W2, all on tensor pipe (tf32), h1 never
// touches global memory. Block = 128 rows, 256 threads (8 warps).
// smem: As[128][132] (Ax tile, tf32), Buf[128][132] (W1 chunk, then P tile),
//       W2s[128][44] (W2 chunk, tf32).
#define PAD_A 132
#define PAD_W 44
__global__ void __launch_bounds__(256) k_fused(const float* __restrict__ W1,
                                               const float* __restrict__ b1,
                                               const float* __restrict__ W2,
                                               int N) {
    extern __shared__ float sm[];
    float* As  = sm;                          // 128*132
    float* Buf = As + 128 * PAD_A;            // 128*132 (B1 chunk / P tile)
    float* W2s = Buf + 128 * PAD_A;           // 128*44

    const int t    = threadIdx.x;
    const int wid  = t >> 5;
    const int lane = t & 31;
    const int g    = lane >> 2;
    const int tg   = lane & 3;
    const int wm   = wid & 3;      // stage1 warp row (4 x 32)
    const int wn   = wid >> 2;     // stage1 warp col (2 x 64)
    const int row0 = blockIdx.x * 128;

    // ---- load A tile (128 rows x 128 k) once, tf32 ----
    #pragma unroll
    for (int i = 0; i < 16; i++) {
        int f  = t + i * 256;       // 0..4095
        int r  = f >> 5;
        int c4 = f & 31;
        int gr = row0 + r;
        float4 v = make_float4(0.f, 0.f, 0.f, 0.f);
        if (gr < N) v = *(const float4*)(g_ax + (size_t)gr * IN_DIM + c4 * 4);
        float4 o;
        o.x = __uint_as_float(f2tf32(v.x));
        o.y = __uint_as_float(f2tf32(v.y));
        o.z = __uint_as_float(f2tf32(v.z));
        o.w = __uint_as_float(f2tf32(v.w));
        *(float4*)&As[r * PAD_A + c4 * 4] = o;
    }

    // stage2 accumulators: rows wid*16+g(+8), cols ni*8+tg*2(+1)
    float acc2[5][4];
    #pragma unroll
    for (int a = 0; a < 5; a++)
        #pragma unroll
        for (int b = 0; b < 4; b++) acc2[a][b] = 0.f;

    for (int nc = 0; nc < 4; nc++) {
        // ---- load W1 chunk [128k][128n] -> Buf (tf32) ----
        #pragma unroll
        for (int i = 0; i < 16; i++) {
            int f  = t + i * 256;
            int k  = f >> 5;
            int c4 = f & 31;
            float4 v = *(const float4*)(W1 + (size_t)k * HID + nc * 128 + c4 * 4);
            float4 o;
            o.x = __uint_as_float(f2tf32(v.x));
            o.y = __uint_as_float(f2tf32(v.y));
            o.z = __uint_as_float(f2tf32(v.z));
            o.w = __uint_as_float(f2tf32(v.w));
            *(float4*)&Buf[k * PAD_A + c4 * 4] = o;
        }
        __syncthreads();

        // ---- stage1 mma: acc1 = A @ W1chunk ----
        float acc1[2][8][4];
        #pragma unroll
        for (int a = 0; a < 2; a++)
            #pragma unroll
            for (int b = 0; b < 8; b++)
                #pragma unroll
                for (int c = 0; c < 4; c++) acc1[a][b][c] = 0.f;

        #pragma unroll
        for (int ks = 0; ks < 16; ks++) {
            const int k0 = ks * 8;
            uint32_t af[2][4];
            #pragma unroll
            for (int mi = 0; mi < 2; mi++) {
                int mb = wm * 32 + mi * 16;
                af[mi][0] = __float_as_uint(As[(mb + g    ) * PAD_A + k0 + tg    ]);
                af[mi][1] = __float_as_uint(As[(mb + g + 8) * PAD_A + k0 + tg    ]);
                af[mi][2] = __float_as_uint(As[(mb + g    ) * PAD_A + k0 + tg + 4]);
                af[mi][3] = __float_as_uint(As[(mb + g + 8) * PAD_A + k0 + tg + 4]);
            }
            uint32_t bf[8][2];
            #pragma unroll
            for (int ni = 0; ni < 8; ni++) {
                int nb = wn * 64 + ni * 8 + g;
                bf[ni][0] = __float_as_uint(Buf[(k0 + tg    ) * PAD_A + nb]);
                bf[ni][1] = __float_as_uint(Buf[(k0 + tg + 4) * PAD_A + nb]);
            }
            #pragma unroll
            for (int mi = 0; mi < 2; mi++)
                #pragma unroll
                for (int ni = 0; ni < 8; ni++) {
                    float* d = acc1[mi][ni];
                    asm volatile(
                        "mma.sync.aligned.m16n8k8.row.col.f32.tf32.tf32.f32 "
                        "{%0,%1,%2,%3}, {%4,%5,%6,%7}, {%8,%9}, {%0,%1,%2,%3};"
                        : "+f"(d[0]), "+f"(d[1]), "+f"(d[2]), "+f"(d[3])
                        : "r"(af[mi][0]), "r"(af[mi][1]), "r"(af[mi][2]), "r"(af[mi][3]),
                          "r"(bf[ni][0]), "r"(bf[ni][1]));
                }
        }
        __syncthreads();   // all reads of Buf (W1 chunk) done

        // ---- bias + relu + tf32 -> P tile into Buf; load W2 chunk ----
        #pragma unroll
        for (int ni = 0; ni < 8; ni++) {
            int lc = wn * 64 + ni * 8 + tg * 2;
            float2 bias = *(const float2*)(b1 + nc * 128 + lc);
            #pragma unroll
            for (int mi = 0; mi < 2; mi++) {
                int lr = wm * 32 + mi * 16 + g;
                float* d = acc1[mi][ni];
                Buf[lr * PAD_A + lc    ] = __uint_as_float(f2tf32(fmaxf(d[0] + bias.x, 0.f)));
                Buf[lr * PAD_A + lc + 1] = __uint_as_float(f2tf32(fmaxf(d[1] + bias.y, 0.f)));
                Buf[(lr + 8) * PAD_A + lc    ] = __uint_as_float(f2tf32(fmaxf(d[2] + bias.x, 0.f)));
                Buf[(lr + 8) * PAD_A + lc + 1] = __uint_as_float(f2tf32(fmaxf(d[3] + bias.y, 0.f)));
            }
        }
        // W2 chunk: [128k][40] -> W2s[128][44] (tf32). 1280 float4, 5/thread
        #pragma unroll
        for (int i = 0; i < 5; i++) {
            int f = t + i * 256;     // 0..1279
            int k = f / 10;
            int q = f % 10;
            float4 v = *(const float4*)(W2 + (size_t)(nc * 128 + k) * NCLS + q * 4);
            float4 o;
            o.x = __uint_as_float(f2tf32(v.x));
            o.y = __uint_as_float(f2tf32(v.y));
            o.z = __uint_as_float(f2tf32(v.z));
            o.w = __uint_as_float(f2tf32(v.w));
            *(float4*)&W2s[k * PAD_W + q * 4] = o;
        }
        __syncthreads();

        // ---- stage2 mma: acc2 += P @ W2chunk ----
        const int m0 = wid * 16;
        #pragma unroll
        for (int ks = 0; ks < 16; ks++) {
            const int k0 = ks * 8;
            uint32_t af[4];
            af[0] = __float_as_uint(Buf[(m0 + g    ) * PAD_A + k0 + tg    ]);
            af[1] = __float_as_uint(Buf[(m0 + g + 8) * PAD_A + k0 + tg    ]);
            af[2] = __float_as_uint(Buf[(m0 + g    ) * PAD_A + k0 + tg + 4]);
            af[3] = __float_as_uint(Buf[(m0 + g + 8) * PAD_A + k0 + tg + 4]);
            #pragma unroll
            for (int ni = 0; ni < 5; ni++) {
                uint32_t b0 = __float_as_uint(W2s[(k0 + tg    ) * PAD_W + ni * 8 + g]);
                uint32_t b1f = __float_as_uint(W2s[(k0 + tg + 4) * PAD_W + ni * 8 + g]);
                float* d = acc2[ni];
                asm volatile(
                    "mma.sync.aligned.m16n8k8.row.col.f32.tf32.tf32.f32 "
                    "{%0,%1,%2,%3}, {%4,%5,%6,%7}, {%8,%9}, {%0,%1,%2,%3};"
                    : "+f"(d[0]), "+f"(d[1]), "+f"(d[2]), "+f"(d[3])
                    : "r"(af[0]), "r"(af[1]), "r"(af[2]), "r"(af[3]),
                      "r"(b0), "r"(b1f));
            }
        }
        __syncthreads();   // protect Buf/W2s for next chunk
    }

    // ---- epilogue: write g2 ----
    const int m0 = row0 + wid * 16;
    #pragma unroll
    for (int ni = 0; ni < 5; ni++) {
        int c = ni * 8 + tg * 2;
        float* d = acc2[ni];
        int r0 = m0 + g;
        if (r0 < N) *(float2*)(g_g2 + (size_t)r0 * NCLS + c) = make_float2(d[0], d[1]);
        int r1 = r0 + 8;
        if (r1 < N) *(float2*)(g_g2 + (size_t)r1 * NCLS + c) = make_float2(d[2], d[3]);
    }
}

// ---------------------------------------------------------------------------
__global__ void k_aggg(const int* __restrict__ src, const int* __restrict__ dst,
                       int E, int U) {
    long gt = (long)blockIdx.x * blockDim.x + threadIdx.x;
    int u = (int)(gt / 10);
    int q = (int)(gt % 10);
    if (u >= U) return;
    int s, d;
    if (u < E) { s = src[u]; d = dst[u]; }
    else       { s = d = u - E; }
    float nrm = g_dinv[s] * g_dinv[d];
    float4 v = *(const float4*)(g_g2 + (size_t)s * NCLS + q * 4);
    float* p = g_oagg + (size_t)d * NCLS + q * 4;
    asm volatile("red.global.add.v4.f32 [%0], {%1,%2,%3,%4};"
                 :: "l"(p), "f"(v.x * nrm), "f"(v.y * nrm),
                    "f"(v.z * nrm), "f"(v.w * nrm) : "memory");
}

// ---------------------------------------------------------------------------
__global__ void k_lsm(const float* __restrict__ b2, float* __restrict__ out, int N) {
    int w = (int)((blockIdx.x * (unsigned)blockDim.x + threadIdx.x) >> 5);
    int l = threadIdx.x & 31;
    if (w >= N) return;
    const float* row = g_oagg + (size_t)w * NCLS;
    float v0 = row[l] + b2[l];
    float v1 = (l < 8) ? (row[32 + l] + b2[32 + l]) : -CUDART_INF_F;
    float m = fmaxf(v0, v1);
    #pragma unroll
    for (int o = 16; o; o >>= 1) m = fmaxf(m, __shfl_xor_sync(0xffffffffu, m, o));
    float s = expf(v0 - m) + ((l < 8) ? expf(v1 - m) : 0.f);
    #pragma unroll
    for (int o = 16; o; o >>= 1) s += __shfl_xor_sync(0xffffffffu, s, o);
    float lse = m + logf(s);
    out[(size_t)w * NCLS + l] = v0 - lse;
    if (l < 8) out[(size_t)w * NCLS + 32 + l] = v1 - lse;
}

// ---------------------------------------------------------------------------
extern "C" void kernel_launch(void* const* d_in, const int* in_sizes, int n_in,
                              void* d_out, int out_size) {
    const float* x  = (const float*)d_in[0];
    const int*   ei = (const int*)  d_in[1];
    const float* W1 = (const float*)d_in[2];
    const float* b1 = (const float*)d_in[3];
    const float* W2 = (const float*)d_in[4];
    const float* b2 = (const float*)d_in[5];
    float* out = (float*)d_out;

    int N = in_sizes[0] / IN_DIM;
    int E = in_sizes[1] / 2;
    const int* src = ei;
    const int* dst = ei + E;
    int U = E + N;

    float *p_ax, *p_oagg;
    cudaGetSymbolAddress((void**)&p_ax,   g_ax);
    cudaGetSymbolAddress((void**)&p_oagg, g_oagg);

    static int smem_set = 0;
    const int SMEM_FUSED = (128 * PAD_A * 2 + 128 * PAD_W) * 4;  // 157,696 B
    if (!smem_set) {
        cudaFuncSetAttribute(k_fused, cudaFuncAttributeMaxDynamicSharedMemorySize,
                             SMEM_FUSED);
        smem_set = 1;
    }

    k_init_deg<<<(N + 255) / 256, 256>>>(N);
    k_zero<<<2048, 256>>>(p_ax,   (size_t)N * IN_DIM);
    k_zero<<<1024, 256>>>(p_oagg, (size_t)N * NCLS);
    k_deg <<<(E + 255) / 256, 256>>>(dst, E);
    k_dinv<<<(N + 255) / 256, 256>>>(N);

    {
        long threads = (long)U * 32;
        int blocks = (int)((threads + 255) / 256);
        k_aggx<<<blocks, 256>>>(x, src, dst, E, U);
    }

    k_fused<<<(N + 127) / 128, 256, SMEM_FUSED>>>(W1, b1, W2, N);

    {
        long threads = (long)U * 10;
        int blocks = (int)((threads + 255) / 256);
        k_aggg<<<blocks, 256>>>(src, dst, E, U);
    }

    {
        long threads = (long)N * 32;
        int blocks = (int)((threads + 255) / 256);
        k_lsm<<<blocks, 256>>>(b2, out, N);
    }
}

// round 4
// speedup vs baseline: 3.4601x; 1.4226x over previous
#include <cuda_runtime.h>
#include <cstdint>
#include <math_constants.h>

#define MAXN 100000
#define IN_DIM 128
#define HID 512
#define NCLS 40

__device__ float g_deg [MAXN];
__device__ float g_dinv[MAXN];
__device__ float g_ax  [(size_t)MAXN * IN_DIM];
__device__ float g_g2  [(size_t)MAXN * NCLS];
__device__ float g_oagg[(size_t)MAXN * NCLS];

// ---------------------------------------------------------------------------
__global__ void k_init_deg(int N) {
    int i = blockIdx.x * blockDim.x + threadIdx.x;
    if (i < N) g_deg[i] = 1.0f;
}

__global__ void k_deg(const int* __restrict__ dst, int E) {
    int e = blockIdx.x * blockDim.x + threadIdx.x;
    if (e < E) atomicAdd(&g_deg[dst[e]], 1.0f);
}

__global__ void k_dinv(int N) {
    int i = blockIdx.x * blockDim.x + threadIdx.x;
    if (i < N) g_dinv[i] = rsqrtf(g_deg[i]);
}

// g_ax[i] = dinv[i]^2 * x[i]   (self-loop contribution; replaces zero-fill)
__global__ void k_initax(const float* __restrict__ x, int N) {
    int idx = blockIdx.x * blockDim.x + threadIdx.x;   // one float4 each
    int node = idx >> 5;
    int c4   = idx & 31;
    if (node >= N) return;
    float s = g_dinv[node]; s *= s;
    float4 v = *(const float4*)(x + (size_t)node * IN_DIM + c4 * 4);
    v.x *= s; v.y *= s; v.z *= s; v.w *= s;
    *(float4*)(g_ax + (size_t)node * IN_DIM + c4 * 4) = v;
}

// g_oagg[i] = dinv[i]^2 * g2[i]
__global__ void k_initoagg(int N) {
    int idx = blockIdx.x * blockDim.x + threadIdx.x;   // one float4 each
    int node = idx / 10;
    int q    = idx % 10;
    if (node >= N) return;
    float s = g_dinv[node]; s *= s;
    float4 v = *(const float4*)(g_g2 + (size_t)node * NCLS + q * 4);
    v.x *= s; v.y *= s; v.z *= s; v.w *= s;
    *(float4*)(g_oagg + (size_t)node * NCLS + q * 4) = v;
}

// ---------------------------------------------------------------------------
__global__ void k_aggx(const float* __restrict__ x, const int* __restrict__ src,
                       const int* __restrict__ dst, int E) {
    int u = (int)((blockIdx.x * (unsigned)blockDim.x + threadIdx.x) >> 5);
    int l = threadIdx.x & 31;
    if (u >= E) return;
    int s = src[u], d = dst[u];
    float nrm = g_dinv[s] * g_dinv[d];
    float4 v = *(const float4*)(x + (size_t)s * IN_DIM + l * 4);
    float* p = g_ax + (size_t)d * IN_DIM + l * 4;
    asm volatile("red.global.add.v4.f32 [%0], {%1,%2,%3,%4};"
                 :: "l"(p), "f"(v.x * nrm), "f"(v.y * nrm),
                    "f"(v.z * nrm), "f"(v.w * nrm) : "memory");
}

// ---------------------------------------------------------------------------
// pack two floats -> bf16x2 (a = low half, b = high half)
__device__ __forceinline__ uint32_t packbf(float a, float b) {
    uint32_t o;
    asm("cvt.rn.bf16x2.f32 %0, %2, %1;" : "=r"(o) : "f"(a), "f"(b));
    return o;
}

// Fused: g2 = relu(Ax @ W1 + b1) @ W2 in bf16 mma (m16n8k16), fp32 accum.
// Block = 128 rows, 256 threads (8 warps). All operands stored as u32 k-pairs.
// smem (u32): As[128][68], Buf[64][136] (W1 pairs) aliased as Ps[128][68],
//             W2p[64][40].
#define AS_S 68    // As / Ps row stride (u32): (4g+tg) bank-perfect
#define BS_S 136   // Bsp row stride (u32):   (8tg+g) bank-perfect
#define W2_S 40    // W2p row stride (u32):   (8tg+g) bank-perfect
__global__ void __launch_bounds__(256, 2)
k_fused(const float* __restrict__ W1, const float* __restrict__ b1,
        const float* __restrict__ W2, int N) {
    extern __shared__ uint32_t sm[];
    uint32_t* As  = sm;                      // 128*68 = 8704
    uint32_t* Buf = As + 128 * AS_S;         // 64*136 = 8704 (== 128*68, aliased as Ps)
    uint32_t* W2p = Buf + 64 * BS_S;         // 64*40  = 2560

    const int t    = threadIdx.x;
    const int wid  = t >> 5;
    const int lane = t & 31;
    const int g    = lane >> 2;
    const int tg   = lane & 3;
    const int wm   = wid & 3;      // stage1 warp row (4 x 32)
    const int wn   = wid >> 2;     // stage1 warp col (2 x 64)
    const int row0 = blockIdx.x * 128;

    // ---- load A tile (128 x 128) once: float4 -> 2 bf16x2 ----
    #pragma unroll
    for (int i = 0; i < 16; i++) {
        int f  = t + i * 256;       // 0..4095
        int r  = f >> 5;
        int c4 = f & 31;
        int gr = row0 + r;
        float4 v = make_float4(0.f, 0.f, 0.f, 0.f);
        if (gr < N) v = *(const float4*)(g_ax + (size_t)gr * IN_DIM + c4 * 4);
        uint2 o;
        o.x = packbf(v.x, v.y);
        o.y = packbf(v.z, v.w);
        *(uint2*)&As[r * AS_S + c4 * 2] = o;
    }

    float acc2[5][4];
    #pragma unroll
    for (int a = 0; a < 5; a++)
        #pragma unroll
        for (int b = 0; b < 4; b++) acc2[a][b] = 0.f;

    for (int nc = 0; nc < 4; nc++) {
        // ---- load W1 chunk as k-pair-packed u32: Bsp[kk][n] ----
        #pragma unroll
        for (int i = 0; i < 8; i++) {
            int f  = t + i * 256;    // 0..2047
            int kk = f >> 5;         // 0..63
            int c4 = f & 31;         // 0..31
            const float* p0 = W1 + (size_t)(2 * kk    ) * HID + nc * 128 + c4 * 4;
            const float* p1 = W1 + (size_t)(2 * kk + 1) * HID + nc * 128 + c4 * 4;
            float4 v0 = *(const float4*)p0;
            float4 v1 = *(const float4*)p1;
            uint4 o;
            o.x = packbf(v0.x, v1.x);
            o.y = packbf(v0.y, v1.y);
            o.z = packbf(v0.z, v1.z);
            o.w = packbf(v0.w, v1.w);
            *(uint4*)&Buf[kk * BS_S + c4 * 4] = o;
        }
        // ---- load W2 chunk k-pair-packed: W2p[kk][n], 2560 u32 ----
        #pragma unroll
        for (int i = 0; i < 10; i++) {
            int f  = t + i * 256;    // 0..2559
            int kk = f / 40;
            int n  = f % 40;
            float a = W2[(size_t)(nc * 128 + 2 * kk    ) * NCLS + n];
            float b = W2[(size_t)(nc * 128 + 2 * kk + 1) * NCLS + n];
            W2p[kk * W2_S + n] = packbf(a, b);
        }
        __syncthreads();

        // ---- stage1 mma: acc1 = A @ W1chunk (K=128, 8 k16 steps) ----
        float acc1[2][8][4];
        #pragma unroll
        for (int a = 0; a < 2; a++)
            #pragma unroll
            for (int b = 0; b < 8; b++)
                #pragma unroll
                for (int c = 0; c < 4; c++) acc1[a][b][c] = 0.f;

        #pragma unroll
        for (int ks = 0; ks < 8; ks++) {
            const int kk0 = ks * 8;
            uint32_t af[2][4];
            #pragma unroll
            for (int mi = 0; mi < 2; mi++) {
                int mb = wm * 32 + mi * 16;
                af[mi][0] = As[(mb + g    ) * AS_S + kk0 + tg    ];
                af[mi][1] = As[(mb + g + 8) * AS_S + kk0 + tg    ];
                af[mi][2] = As[(mb + g    ) * AS_S + kk0 + tg + 4];
                af[mi][3] = As[(mb + g + 8) * AS_S + kk0 + tg + 4];
            }
            uint32_t bf[8][2];
            #pragma unroll
            for (int ni = 0; ni < 8; ni++) {
                int nb = wn * 64 + ni * 8 + g;
                bf[ni][0] = Buf[(kk0 + tg    ) * BS_S + nb];
                bf[ni][1] = Buf[(kk0 + tg + 4) * BS_S + nb];
            }
            #pragma unroll
            for (int mi = 0; mi < 2; mi++)
                #pragma unroll
                for (int ni = 0; ni < 8; ni++) {
                    float* d = acc1[mi][ni];
                    asm volatile(
                        "mma.sync.aligned.m16n8k16.row.col.f32.bf16.bf16.f32 "
                        "{%0,%1,%2,%3}, {%4,%5,%6,%7}, {%8,%9}, {%0,%1,%2,%3};"
                        : "+f"(d[0]), "+f"(d[1]), "+f"(d[2]), "+f"(d[3])
                        : "r"(af[mi][0]), "r"(af[mi][1]), "r"(af[mi][2]), "r"(af[mi][3]),
                          "r"(bf[ni][0]), "r"(bf[ni][1]));
                }
        }
        __syncthreads();   // all reads of Buf done

        // ---- bias + relu -> P (bf16 pairs) into Buf (as Ps[128][68]) ----
        #pragma unroll
        for (int ni = 0; ni < 8; ni++) {
            int lc = wn * 64 + ni * 8 + tg * 2;          // stage1 local col
            int kk = lc >> 1;                            // P u32 col
            float2 bias = *(const float2*)(b1 + nc * 128 + lc);
            #pragma unroll
            for (int mi = 0; mi < 2; mi++) {
                int lr = wm * 32 + mi * 16 + g;
                float* d = acc1[mi][ni];
                Buf[lr * AS_S + kk] =
                    packbf(fmaxf(d[0] + bias.x, 0.f), fmaxf(d[1] + bias.y, 0.f));
                Buf[(lr + 8) * AS_S + kk] =
                    packbf(fmaxf(d[2] + bias.x, 0.f), fmaxf(d[3] + bias.y, 0.f));
            }
        }
        __syncthreads();

        // ---- stage2 mma: acc2 += P @ W2chunk (K=128, 8 k16 steps) ----
        const int m0 = wid * 16;
        #pragma unroll
        for (int ks = 0; ks < 8; ks++) {
            const int kk0 = ks * 8;
            uint32_t af[4];
            af[0] = Buf[(m0 + g    ) * AS_S + kk0 + tg    ];
            af[1] = Buf[(m0 + g + 8) * AS_S + kk0 + tg    ];
            af[2] = Buf[(m0 + g    ) * AS_S + kk0 + tg + 4];
            af[3] = Buf[(m0 + g + 8) * AS_S + kk0 + tg + 4];
            #pragma unroll
            for (int ni = 0; ni < 5; ni++) {
                uint32_t b0 = W2p[(kk0 + tg    ) * W2_S + ni * 8 + g];
                uint32_t b1f = W2p[(kk0 + tg + 4) * W2_S + ni * 8 + g];
                float* d = acc2[ni];
                asm volatile(
                    "mma.sync.aligned.m16n8k16.row.col.f32.bf16.bf16.f32 "
                    "{%0,%1,%2,%3}, {%4,%5,%6,%7}, {%8,%9}, {%0,%1,%2,%3};"
                    : "+f"(d[0]), "+f"(d[1]), "+f"(d[2]), "+f"(d[3])
                    : "r"(af[0]), "r"(af[1]), "r"(af[2]), "r"(af[3]),
                      "r"(b0), "r"(b1f));
            }
        }
        __syncthreads();   // protect Buf/W2p for next chunk
    }

    // ---- epilogue: write g2 ----
    const int m0 = row0 + wid * 16;
    #pragma unroll
    for (int ni = 0; ni < 5; ni++) {
        int c = ni * 8 + tg * 2;
        float* d = acc2[ni];
        int r0 = m0 + g;
        if (r0 < N) *(float2*)(g_g2 + (size_t)r0 * NCLS + c) = make_float2(d[0], d[1]);
        int r1 = r0 + 8;
        if (r1 < N) *(float2*)(g_g2 + (size_t)r1 * NCLS + c) = make_float2(d[2], d[3]);
    }
}

// ---------------------------------------------------------------------------
__global__ void k_aggg(const int* __restrict__ src, const int* __restrict__ dst,
                       int E) {
    long gt = (long)blockIdx.x * blockDim.x + threadIdx.x;
    int u = (int)(gt / 10);
    int q = (int)(gt % 10);
    if (u >= E) return;
    int s = src[u], d = dst[u];
    float nrm = g_dinv[s] * g_dinv[d];
    float4 v = *(const float4*)(g_g2 + (size_t)s * NCLS + q * 4);
    float* p = g_oagg + (size_t)d * NCLS + q * 4;
    asm volatile("red.global.add.v4.f32 [%0], {%1,%2,%3,%4};"
                 :: "l"(p), "f"(v.x * nrm), "f"(v.y * nrm),
                    "f"(v.z * nrm), "f"(v.w * nrm) : "memory");
}

// ---------------------------------------------------------------------------
__global__ void k_lsm(const float* __restrict__ b2, float* __restrict__ out, int N) {
    int w = (int)((blockIdx.x * (unsigned)blockDim.x + threadIdx.x) >> 5);
    int l = threadIdx.x & 31;
    if (w >= N) return;
    const float* row = g_oagg + (size_t)w * NCLS;
    float v0 = row[l] + b2[l];
    float v1 = (l < 8) ? (row[32 + l] + b2[32 + l]) : -CUDART_INF_F;
    float m = fmaxf(v0, v1);
    #pragma unroll
    for (int o = 16; o; o >>= 1) m = fmaxf(m, __shfl_xor_sync(0xffffffffu, m, o));
    float s = expf(v0 - m) + ((l < 8) ? expf(v1 - m) : 0.f);
    #pragma unroll
    for (int o = 16; o; o >>= 1) s += __shfl_xor_sync(0xffffffffu, s, o);
    float lse = m + logf(s);
    out[(size_t)w * NCLS + l] = v0 - lse;
    if (l < 8) out[(size_t)w * NCLS + 32 + l] = v1 - lse;
}

// ---------------------------------------------------------------------------
extern "C" void kernel_launch(void* const* d_in, const int* in_sizes, int n_in,
                              void* d_out, int out_size) {
    const float* x  = (const float*)d_in[0];
    const int*   ei = (const int*)  d_in[1];
    const float* W1 = (const float*)d_in[2];
    const float* b1 = (const float*)d_in[3];
    const float* W2 = (const float*)d_in[4];
    const float* b2 = (const float*)d_in[5];
    float* out = (float*)d_out;

    int N = in_sizes[0] / IN_DIM;
    int E = in_sizes[1] / 2;
    const int* src = ei;
    const int* dst = ei + E;

    static int smem_set = 0;
    const int SMEM_FUSED = (128 * AS_S + 64 * BS_S + 64 * W2_S) * 4;  // 79,872 B
    if (!smem_set) {
        cudaFuncSetAttribute(k_fused, cudaFuncAttributeMaxDynamicSharedMemorySize,
                             SMEM_FUSED);
        smem_set = 1;
    }

    k_init_deg<<<(N + 255) / 256, 256>>>(N);
    k_deg <<<(E + 255) / 256, 256>>>(dst, E);
    k_dinv<<<(N + 255) / 256, 256>>>(N);

    // g_ax = dinv^2 * x  (self-loops)
    {
        long threads = (long)N * 32;
        k_initax<<<(int)((threads + 255) / 256), 256>>>(x, N);
    }
    // edges into g_ax
    {
        long threads = (long)E * 32;
        k_aggx<<<(int)((threads + 255) / 256), 256>>>(x, src, dst, E);
    }

    k_fused<<<(N + 127) / 128, 256, SMEM_FUSED>>>(W1, b1, W2, N);

    // g_oagg = dinv^2 * g2 (self-loops)
    {
        long threads = (long)N * 10;
        k_initoagg<<<(int)((threads + 255) / 256), 256>>>(N);
    }
    // edges into g_oagg
    {
        long threads = (long)E * 10;
        k_aggg<<<(int)((threads + 255) / 256), 256>>>(src, dst, E);
    }

    {
        long threads = (long)N * 32;
        k_lsm<<<(int)((threads + 255) / 256), 256>>>(b2, out, N);
    }
}

// round 5
// speedup vs baseline: 4.1696x; 1.2050x over previous
#include <cuda_runtime.h>
#include <cstdint>
#include <math_constants.h>

#define MAXN 100000
#define MAXE 500000
#define IN_DIM 128
#define HID 512
#define NCLS 40
#define SCAN_BLK 512   // elements per scan block (256 threads x 2)

__device__ float g_deg   [MAXN];
__device__ float g_dinv  [MAXN];
__device__ int   g_rowptr[MAXN + 1];
__device__ int   g_cursor[MAXN];
__device__ int   g_bsum  [256];
__device__ int   g_csrc  [MAXE];
__device__ float g_ax    [(size_t)MAXN * IN_DIM];
__device__ float g_g2    [(size_t)MAXN * NCLS];

// ---------------------------------------------------------------------------
__global__ void k_init_deg(int N) {
    int i = blockIdx.x * blockDim.x + threadIdx.x;
    if (i < N) g_deg[i] = 1.0f;
}

__global__ void k_deg(const int* __restrict__ dst, int E) {
    int e = blockIdx.x * blockDim.x + threadIdx.x;
    if (e < E) atomicAdd(&g_deg[dst[e]], 1.0f);
}

__global__ void k_dinv(int N) {
    int i = blockIdx.x * blockDim.x + threadIdx.x;
    if (i < N) g_dinv[i] = rsqrtf(g_deg[i]);
}

// ---------------------------------------------------------------------------
// 3-phase exclusive scan of cnt[i] = deg[i]-1 (in-degree w/o self loop)
__global__ void k_scan_a(int N) {
    __shared__ int s[256];
    int t = threadIdx.x;
    int base = blockIdx.x * SCAN_BLK;
    int i0 = base + 2 * t, i1 = i0 + 1;
    int c0 = (i0 < N) ? (int)(g_deg[i0] - 0.5f) : 0;   // deg-1, deg>=1
    int c1 = (i1 < N) ? (int)(g_deg[i1] - 0.5f) : 0;
    int sum = c0 + c1;
    s[t] = sum;
    __syncthreads();
    #pragma unroll
    for (int off = 1; off < 256; off <<= 1) {
        int v = (t >= off) ? s[t - off] : 0;
        __syncthreads();
        s[t] += v;
        __syncthreads();
    }
    int ex = s[t] - sum;   // exclusive within block
    if (i0 < N) g_rowptr[i0] = ex;
    if (i1 < N) g_rowptr[i1] = ex + c0;
    if (t == 255) g_bsum[blockIdx.x] = s[255];
}

__global__ void k_scan_b(int NB) {
    __shared__ int s[256];
    int t = threadIdx.x;
    int v0 = (t < NB) ? g_bsum[t] : 0;
    s[t] = v0;
    __syncthreads();
    #pragma unroll
    for (int off = 1; off < 256; off <<= 1) {
        int v = (t >= off) ? s[t - off] : 0;
        __syncthreads();
        s[t] += v;
        __syncthreads();
    }
    if (t < NB) g_bsum[t] = s[t] - v0;   // exclusive block offsets
}

__global__ void k_scan_c(int N, int E) {
    int i = blockIdx.x * blockDim.x + threadIdx.x;
    if (i < N) {
        int v = g_rowptr[i] + g_bsum[i / SCAN_BLK];
        g_rowptr[i] = v;
        g_cursor[i] = v;
    }
    if (i == 0) g_rowptr[N] = E;
}

__global__ void k_scatter(const int* __restrict__ src, const int* __restrict__ dst,
                          int E) {
    int e = blockIdx.x * blockDim.x + threadIdx.x;
    if (e >= E) return;
    int pos = atomicAdd(&g_cursor[dst[e]], 1);
    g_csrc[pos] = src[e];
}

// ---------------------------------------------------------------------------
// g_ax[i] = dinv[i] * sum_{s in N(i)} dinv[s]*x[s]  +  dinv[i]^2 * x[i]
// one warp per node, float4 per lane (128 floats)
__global__ void k_gax(const float* __restrict__ x, int N) {
    int i = (int)((blockIdx.x * (unsigned)blockDim.x + threadIdx.x) >> 5);
    int l = threadIdx.x & 31;
    if (i >= N) return;
    int b  = g_rowptr[i];
    int e2 = g_rowptr[i + 1];
    float4 acc = make_float4(0.f, 0.f, 0.f, 0.f);
    for (int j = b; j < e2; j++) {
        int s = g_csrc[j];
        float w = g_dinv[s];
        float4 v = *(const float4*)(x + (size_t)s * IN_DIM + l * 4);
        acc.x += w * v.x; acc.y += w * v.y; acc.z += w * v.z; acc.w += w * v.w;
    }
    float di = g_dinv[i];
    float d2 = di * di;
    float4 xi = *(const float4*)(x + (size_t)i * IN_DIM + l * 4);
    float4 o;
    o.x = di * acc.x + d2 * xi.x;
    o.y = di * acc.y + d2 * xi.y;
    o.z = di * acc.z + d2 * xi.z;
    o.w = di * acc.w + d2 * xi.w;
    *(float4*)(g_ax + (size_t)i * IN_DIM + l * 4) = o;
}

// ---------------------------------------------------------------------------
__device__ __forceinline__ uint32_t packbf(float a, float b) {
    uint32_t o;
    asm("cvt.rn.bf16x2.f32 %0, %2, %1;" : "=r"(o) : "f"(a), "f"(b));
    return o;
}

// Fused tensor-core kernel: g2 = relu(Ax @ W1 + b1) @ W2 (bf16 mma, fp32 acc)
#define AS_S 68
#define BS_S 136
#define W2_S 40
__global__ void __launch_bounds__(256, 2)
k_fused(const float* __restrict__ W1, const float* __restrict__ b1,
        const float* __restrict__ W2, int N) {
    extern __shared__ uint32_t sm[];
    uint32_t* As  = sm;                      // 128*68
    uint32_t* Buf = As + 128 * AS_S;         // 64*136, aliased as Ps[128][68]
    uint32_t* W2p = Buf + 64 * BS_S;         // 64*40

    const int t    = threadIdx.x;
    const int wid  = t >> 5;
    const int lane = t & 31;
    const int g    = lane >> 2;
    const int tg   = lane & 3;
    const int wm   = wid & 3;
    const int wn   = wid >> 2;
    const int row0 = blockIdx.x * 128;

    #pragma unroll
    for (int i = 0; i < 16; i++) {
        int f  = t + i * 256;
        int r  = f >> 5;
        int c4 = f & 31;
        int gr = row0 + r;
        float4 v = make_float4(0.f, 0.f, 0.f, 0.f);
        if (gr < N) v = *(const float4*)(g_ax + (size_t)gr * IN_DIM + c4 * 4);
        uint2 o;
        o.x = packbf(v.x, v.y);
        o.y = packbf(v.z, v.w);
        *(uint2*)&As[r * AS_S + c4 * 2] = o;
    }

    float acc2[5][4];
    #pragma unroll
    for (int a = 0; a < 5; a++)
        #pragma unroll
        for (int b = 0; b < 4; b++) acc2[a][b] = 0.f;

    for (int nc = 0; nc < 4; nc++) {
        #pragma unroll
        for (int i = 0; i < 8; i++) {
            int f  = t + i * 256;
            int kk = f >> 5;
            int c4 = f & 31;
            float4 v0 = *(const float4*)(W1 + (size_t)(2 * kk    ) * HID + nc * 128 + c4 * 4);
            float4 v1 = *(const float4*)(W1 + (size_t)(2 * kk + 1) * HID + nc * 128 + c4 * 4);
            uint4 o;
            o.x = packbf(v0.x, v1.x);
            o.y = packbf(v0.y, v1.y);
            o.z = packbf(v0.z, v1.z);
            o.w = packbf(v0.w, v1.w);
            *(uint4*)&Buf[kk * BS_S + c4 * 4] = o;
        }
        #pragma unroll
        for (int i = 0; i < 10; i++) {
            int f  = t + i * 256;
            int kk = f / 40;
            int n  = f % 40;
            float a = W2[(size_t)(nc * 128 + 2 * kk    ) * NCLS + n];
            float b = W2[(size_t)(nc * 128 + 2 * kk + 1) * NCLS + n];
            W2p[kk * W2_S + n] = packbf(a, b);
        }
        __syncthreads();

        float acc1[2][8][4];
        #pragma unroll
        for (int a = 0; a < 2; a++)
            #pragma unroll
            for (int b = 0; b < 8; b++)
                #pragma unroll
                for (int c = 0; c < 4; c++) acc1[a][b][c] = 0.f;

        #pragma unroll
        for (int ks = 0; ks < 8; ks++) {
            const int kk0 = ks * 8;
            uint32_t af[2][4];
            #pragma unroll
            for (int mi = 0; mi < 2; mi++) {
                int mb = wm * 32 + mi * 16;
                af[mi][0] = As[(mb + g    ) * AS_S + kk0 + tg    ];
                af[mi][1] = As[(mb + g + 8) * AS_S + kk0 + tg    ];
                af[mi][2] = As[(mb + g    ) * AS_S + kk0 + tg + 4];
                af[mi][3] = As[(mb + g + 8) * AS_S + kk0 + tg + 4];
            }
            uint32_t bf[8][2];
            #pragma unroll
            for (int ni = 0; ni < 8; ni++) {
                int nb = wn * 64 + ni * 8 + g;
                bf[ni][0] = Buf[(kk0 + tg    ) * BS_S + nb];
                bf[ni][1] = Buf[(kk0 + tg + 4) * BS_S + nb];
            }
            #pragma unroll
            for (int mi = 0; mi < 2; mi++)
                #pragma unroll
                for (int ni = 0; ni < 8; ni++) {
                    float* d = acc1[mi][ni];
                    asm volatile(
                        "mma.sync.aligned.m16n8k16.row.col.f32.bf16.bf16.f32 "
                        "{%0,%1,%2,%3}, {%4,%5,%6,%7}, {%8,%9}, {%0,%1,%2,%3};"
                        : "+f"(d[0]), "+f"(d[1]), "+f"(d[2]), "+f"(d[3])
                        : "r"(af[mi][0]), "r"(af[mi][1]), "r"(af[mi][2]), "r"(af[mi][3]),
                          "r"(bf[ni][0]), "r"(bf[ni][1]));
                }
        }
        __syncthreads();

        #pragma unroll
        for (int ni = 0; ni < 8; ni++) {
            int lc = wn * 64 + ni * 8 + tg * 2;
            int kk = lc >> 1;
            float2 bias = *(const float2*)(b1 + nc * 128 + lc);
            #pragma unroll
            for (int mi = 0; mi < 2; mi++) {
                int lr = wm * 32 + mi * 16 + g;
                float* d = acc1[mi][ni];
                Buf[lr * AS_S + kk] =
                    packbf(fmaxf(d[0] + bias.x, 0.f), fmaxf(d[1] + bias.y, 0.f));
                Buf[(lr + 8) * AS_S + kk] =
                    packbf(fmaxf(d[2] + bias.x, 0.f), fmaxf(d[3] + bias.y, 0.f));
            }
        }
        __syncthreads();

        const int m0 = wid * 16;
        #pragma unroll
        for (int ks = 0; ks < 8; ks++) {
            const int kk0 = ks * 8;
            uint32_t af[4];
            af[0] = Buf[(m0 + g    ) * AS_S + kk0 + tg    ];
            af[1] = Buf[(m0 + g + 8) * AS_S + kk0 + tg    ];
            af[2] = Buf[(m0 + g    ) * AS_S + kk0 + tg + 4];
            af[3] = Buf[(m0 + g + 8) * AS_S + kk0 + tg + 4];
            #pragma unroll
            for (int ni = 0; ni < 5; ni++) {
                uint32_t b0 = W2p[(kk0 + tg    ) * W2_S + ni * 8 + g];
                uint32_t b1f = W2p[(kk0 + tg + 4) * W2_S + ni * 8 + g];
                float* d = acc2[ni];
                asm volatile(
                    "mma.sync.aligned.m16n8k16.row.col.f32.bf16.bf16.f32 "
                    "{%0,%1,%2,%3}, {%4,%5,%6,%7}, {%8,%9}, {%0,%1,%2,%3};"
                    : "+f"(d[0]), "+f"(d[1]), "+f"(d[2]), "+f"(d[3])
                    : "r"(af[0]), "r"(af[1]), "r"(af[2]), "r"(af[3]),
                      "r"(b0), "r"(b1f));
            }
        }
        __syncthreads();
    }

    const int m0 = row0 + wid * 16;
    #pragma unroll
    for (int ni = 0; ni < 5; ni++) {
        int c = ni * 8 + tg * 2;
        float* d = acc2[ni];
        int r0 = m0 + g;
        if (r0 < N) *(float2*)(g_g2 + (size_t)r0 * NCLS + c) = make_float2(d[0], d[1]);
        int r1 = r0 + 8;
        if (r1 < N) *(float2*)(g_g2 + (size_t)r1 * NCLS + c) = make_float2(d[2], d[3]);
    }
}

// ---------------------------------------------------------------------------
// Fused: CSR-gather aggregation of g2 + bias + log_softmax -> out.
// One warp per node; lane l covers col l, lanes<8 also col 32+l.
__global__ void k_gout(const float* __restrict__ b2, float* __restrict__ out, int N) {
    int i = (int)((blockIdx.x * (unsigned)blockDim.x + threadIdx.x) >> 5);
    int l = threadIdx.x & 31;
    if (i >= N) return;
    int b  = g_rowptr[i];
    int e2 = g_rowptr[i + 1];
    float a0 = 0.f, a1 = 0.f;
    for (int j = b; j < e2; j++) {
        int s = g_csrc[j];
        float w = g_dinv[s];
        const float* row = g_g2 + (size_t)s * NCLS;
        a0 += w * row[l];
        if (l < 8) a1 += w * row[32 + l];
    }
    float di = g_dinv[i];
    float d2 = di * di;
    const float* self = g_g2 + (size_t)i * NCLS;
    float v0 = di * a0 + d2 * self[l] + b2[l];
    float v1 = (l < 8) ? (di * a1 + d2 * self[32 + l] + b2[32 + l]) : -CUDART_INF_F;

    float m = fmaxf(v0, v1);
    #pragma unroll
    for (int o = 16; o; o >>= 1) m = fmaxf(m, __shfl_xor_sync(0xffffffffu, m, o));
    float s = expf(v0 - m) + ((l < 8) ? expf(v1 - m) : 0.f);
    #pragma unroll
    for (int o = 16; o; o >>= 1) s += __shfl_xor_sync(0xffffffffu, s, o);
    float lse = m + logf(s);
    out[(size_t)i * NCLS + l] = v0 - lse;
    if (l < 8) out[(size_t)i * NCLS + 32 + l] = v1 - lse;
}

// ---------------------------------------------------------------------------
extern "C" void kernel_launch(void* const* d_in, const int* in_sizes, int n_in,
                              void* d_out, int out_size) {
    const float* x  = (const float*)d_in[0];
    const int*   ei = (const int*)  d_in[1];
    const float* W1 = (const float*)d_in[2];
    const float* b1 = (const float*)d_in[3];
    const float* W2 = (const float*)d_in[4];
    const float* b2 = (const float*)d_in[5];
    float* out = (float*)d_out;

    int N = in_sizes[0] / IN_DIM;
    int E = in_sizes[1] / 2;
    const int* src = ei;
    const int* dst = ei + E;

    static int smem_set = 0;
    const int SMEM_FUSED = (128 * AS_S + 64 * BS_S + 64 * W2_S) * 4;  // 79,872 B
    if (!smem_set) {
        cudaFuncSetAttribute(k_fused, cudaFuncAttributeMaxDynamicSharedMemorySize,
                             SMEM_FUSED);
        smem_set = 1;
    }

    int NB = (N + SCAN_BLK - 1) / SCAN_BLK;   // 196 <= 256

    k_init_deg<<<(N + 255) / 256, 256>>>(N);
    k_deg <<<(E + 255) / 256, 256>>>(dst, E);
    k_dinv<<<(N + 255) / 256, 256>>>(N);

    // CSR build
    k_scan_a<<<NB, 256>>>(N);
    k_scan_b<<<1, 256>>>(NB);
    k_scan_c<<<(N + 255) / 256, 256>>>(N, E);
    k_scatter<<<(E + 255) / 256, 256>>>(src, dst, E);

    // layer-1 aggregation (gather, atomic-free)
    {
        long threads = (long)N * 32;
        k_gax<<<(int)((threads + 255) / 256), 256>>>(x, N);
    }

    // fused GEMM1+relu+GEMM2
    k_fused<<<(N + 127) / 128, 256, SMEM_FUSED>>>(W1, b1, W2, N);

    // layer-2 aggregation + bias + log_softmax
    {
        long threads = (long)N * 32;
        k_gout<<<(int)((threads + 255) / 256), 256>>>(b2, out, N);
    }
}

// round 6
// speedup vs baseline: 4.2231x; 1.0128x over previous
#include <cuda_runtime.h>
#include <cstdint>
#include <math_constants.h>

#define MAXN 100000
#define MAXE 500000
#define IN_DIM 128
#define HID 512
#define NCLS 40
#define SCAN_BLK 512   // elements per scan block (256 threads x 2)

__device__ int   g_degi  [MAXN];
__device__ float g_dinv  [MAXN];
__device__ int   g_rowptr[MAXN + 1];
__device__ int   g_cursor[MAXN];
__device__ int   g_bsum  [256];
__device__ int   g_csrc  [MAXE];
__device__ float g_ax    [(size_t)MAXN * IN_DIM];
__device__ float g_g2    [(size_t)MAXN * NCLS];

// ---------------------------------------------------------------------------
__global__ void k_deg(const int* __restrict__ dst, int E) {
    int e = blockIdx.x * blockDim.x + threadIdx.x;
    if (e < E) atomicAdd(&g_degi[dst[e]], 1);
}

// exclusive scan of g_degi (phase A) + dinv computation folded in
__global__ void k_scan_a(int N) {
    __shared__ int s[256];
    int t = threadIdx.x;
    int base = blockIdx.x * SCAN_BLK;
    int i0 = base + 2 * t, i1 = i0 + 1;
    int c0 = (i0 < N) ? g_degi[i0] : 0;
    int c1 = (i1 < N) ? g_degi[i1] : 0;
    if (i0 < N) g_dinv[i0] = rsqrtf((float)(c0 + 1));
    if (i1 < N) g_dinv[i1] = rsqrtf((float)(c1 + 1));
    int sum = c0 + c1;
    s[t] = sum;
    __syncthreads();
    #pragma unroll
    for (int off = 1; off < 256; off <<= 1) {
        int v = (t >= off) ? s[t - off] : 0;
        __syncthreads();
        s[t] += v;
        __syncthreads();
    }
    int ex = s[t] - sum;
    if (i0 < N) g_rowptr[i0] = ex;
    if (i1 < N) g_rowptr[i1] = ex + c0;
    if (t == 255) g_bsum[blockIdx.x] = s[255];
}

__global__ void k_scan_b(int NB) {
    __shared__ int s[256];
    int t = threadIdx.x;
    int v0 = (t < NB) ? g_bsum[t] : 0;
    s[t] = v0;
    __syncthreads();
    #pragma unroll
    for (int off = 1; off < 256; off <<= 1) {
        int v = (t >= off) ? s[t - off] : 0;
        __syncthreads();
        s[t] += v;
        __syncthreads();
    }
    if (t < NB) g_bsum[t] = s[t] - v0;
}

__global__ void k_scan_c(int N, int E) {
    int i = blockIdx.x * blockDim.x + threadIdx.x;
    if (i < N) {
        int v = g_rowptr[i] + g_bsum[i / SCAN_BLK];
        g_rowptr[i] = v;
        g_cursor[i] = v;
    }
    if (i == 0) g_rowptr[N] = E;
}

__global__ void k_scatter(const int* __restrict__ src, const int* __restrict__ dst,
                          int E) {
    int e = blockIdx.x * blockDim.x + threadIdx.x;
    if (e >= E) return;
    int pos = atomicAdd(&g_cursor[dst[e]], 1);
    g_csrc[pos] = src[e];
}

// ---------------------------------------------------------------------------
// g_ax[i] = dinv[i] * sum_{s in N(i)} dinv[s]*x[s]  +  dinv[i]^2 * x[i]
// one warp per node, float4 per lane; 4-way unrolled for MLP
__global__ void k_gax(const float* __restrict__ x, int N) {
    int i = (int)((blockIdx.x * (unsigned)blockDim.x + threadIdx.x) >> 5);
    int l = threadIdx.x & 31;
    if (i >= N) return;
    int b  = g_rowptr[i];
    int e2 = g_rowptr[i + 1];
    float4 acc = make_float4(0.f, 0.f, 0.f, 0.f);
    int j = b;
    for (; j + 4 <= e2; j += 4) {
        int s0 = g_csrc[j], s1 = g_csrc[j + 1], s2 = g_csrc[j + 2], s3 = g_csrc[j + 3];
        float w0 = g_dinv[s0], w1 = g_dinv[s1], w2 = g_dinv[s2], w3 = g_dinv[s3];
        float4 v0 = *(const float4*)(x + (size_t)s0 * IN_DIM + l * 4);
        float4 v1 = *(const float4*)(x + (size_t)s1 * IN_DIM + l * 4);
        float4 v2 = *(const float4*)(x + (size_t)s2 * IN_DIM + l * 4);
        float4 v3 = *(const float4*)(x + (size_t)s3 * IN_DIM + l * 4);
        acc.x += w0 * v0.x + w1 * v1.x + w2 * v2.x + w3 * v3.x;
        acc.y += w0 * v0.y + w1 * v1.y + w2 * v2.y + w3 * v3.y;
        acc.z += w0 * v0.z + w1 * v1.z + w2 * v2.z + w3 * v3.z;
        acc.w += w0 * v0.w + w1 * v1.w + w2 * v2.w + w3 * v3.w;
    }
    for (; j < e2; j++) {
        int s = g_csrc[j];
        float w = g_dinv[s];
        float4 v = *(const float4*)(x + (size_t)s * IN_DIM + l * 4);
        acc.x += w * v.x; acc.y += w * v.y; acc.z += w * v.z; acc.w += w * v.w;
    }
    float di = g_dinv[i];
    float d2 = di * di;
    float4 xi = *(const float4*)(x + (size_t)i * IN_DIM + l * 4);
    float4 o;
    o.x = di * acc.x + d2 * xi.x;
    o.y = di * acc.y + d2 * xi.y;
    o.z = di * acc.z + d2 * xi.z;
    o.w = di * acc.w + d2 * xi.w;
    *(float4*)(g_ax + (size_t)i * IN_DIM + l * 4) = o;
}

// ---------------------------------------------------------------------------
__device__ __forceinline__ uint32_t packbf(float a, float b) {
    uint32_t o;
    asm("cvt.rn.bf16x2.f32 %0, %2, %1;" : "=r"(o) : "f"(a), "f"(b));
    return o;
}

// Fused tensor-core kernel: g2 = relu(Ax @ W1 + b1) @ W2 (bf16 mma, fp32 acc)
#define AS_S 68
#define BS_S 136
#define W2_S 40
__global__ void __launch_bounds__(256, 2)
k_fused(const float* __restrict__ W1, const float* __restrict__ b1,
        const float* __restrict__ W2, int N) {
    extern __shared__ uint32_t sm[];
    uint32_t* As  = sm;                      // 128*68
    uint32_t* Buf = As + 128 * AS_S;         // 64*136, aliased as Ps[128][68]
    uint32_t* W2p = Buf + 64 * BS_S;         // 64*40

    const int t    = threadIdx.x;
    const int wid  = t >> 5;
    const int lane = t & 31;
    const int g    = lane >> 2;
    const int tg   = lane & 3;
    const int wm   = wid & 3;
    const int wn   = wid >> 2;
    const int row0 = blockIdx.x * 128;

    #pragma unroll
    for (int i = 0; i < 16; i++) {
        int f  = t + i * 256;
        int r  = f >> 5;
        int c4 = f & 31;
        int gr = row0 + r;
        float4 v = make_float4(0.f, 0.f, 0.f, 0.f);
        if (gr < N) v = *(const float4*)(g_ax + (size_t)gr * IN_DIM + c4 * 4);
        uint2 o;
        o.x = packbf(v.x, v.y);
        o.y = packbf(v.z, v.w);
        *(uint2*)&As[r * AS_S + c4 * 2] = o;
    }

    float acc2[5][4];
    #pragma unroll
    for (int a = 0; a < 5; a++)
        #pragma unroll
        for (int b = 0; b < 4; b++) acc2[a][b] = 0.f;

    for (int nc = 0; nc < 4; nc++) {
        #pragma unroll
        for (int i = 0; i < 8; i++) {
            int f  = t + i * 256;
            int kk = f >> 5;
            int c4 = f & 31;
            float4 v0 = *(const float4*)(W1 + (size_t)(2 * kk    ) * HID + nc * 128 + c4 * 4);
            float4 v1 = *(const float4*)(W1 + (size_t)(2 * kk + 1) * HID + nc * 128 + c4 * 4);
            uint4 o;
            o.x = packbf(v0.x, v1.x);
            o.y = packbf(v0.y, v1.y);
            o.z = packbf(v0.z, v1.z);
            o.w = packbf(v0.w, v1.w);
            *(uint4*)&Buf[kk * BS_S + c4 * 4] = o;
        }
        #pragma unroll
        for (int i = 0; i < 10; i++) {
            int f  = t + i * 256;
            int kk = f / 40;
            int n  = f % 40;
            float a = W2[(size_t)(nc * 128 + 2 * kk    ) * NCLS + n];
            float b = W2[(size_t)(nc * 128 + 2 * kk + 1) * NCLS + n];
            W2p[kk * W2_S + n] = packbf(a, b);
        }
        __syncthreads();

        float acc1[2][8][4];
        #pragma unroll
        for (int a = 0; a < 2; a++)
            #pragma unroll
            for (int b = 0; b < 8; b++)
                #pragma unroll
                for (int c = 0; c < 4; c++) acc1[a][b][c] = 0.f;

        #pragma unroll
        for (int ks = 0; ks < 8; ks++) {
            const int kk0 = ks * 8;
            uint32_t af[2][4];
            #pragma unroll
            for (int mi = 0; mi < 2; mi++) {
                int mb = wm * 32 + mi * 16;
                af[mi][0] = As[(mb + g    ) * AS_S + kk0 + tg    ];
                af[mi][1] = As[(mb + g + 8) * AS_S + kk0 + tg    ];
                af[mi][2] = As[(mb + g    ) * AS_S + kk0 + tg + 4];
                af[mi][3] = As[(mb + g + 8) * AS_S + kk0 + tg + 4];
            }
            uint32_t bf[8][2];
            #pragma unroll
            for (int ni = 0; ni < 8; ni++) {
                int nb = wn * 64 + ni * 8 + g;
                bf[ni][0] = Buf[(kk0 + tg    ) * BS_S + nb];
                bf[ni][1] = Buf[(kk0 + tg + 4) * BS_S + nb];
            }
            #pragma unroll
            for (int mi = 0; mi < 2; mi++)
                #pragma unroll
                for (int ni = 0; ni < 8; ni++) {
                    float* d = acc1[mi][ni];
                    asm volatile(
                        "mma.sync.aligned.m16n8k16.row.col.f32.bf16.bf16.f32 "
                        "{%0,%1,%2,%3}, {%4,%5,%6,%7}, {%8,%9}, {%0,%1,%2,%3};"
                        : "+f"(d[0]), "+f"(d[1]), "+f"(d[2]), "+f"(d[3])
                        : "r"(af[mi][0]), "r"(af[mi][1]), "r"(af[mi][2]), "r"(af[mi][3]),
                          "r"(bf[ni][0]), "r"(bf[ni][1]));
                }
        }
        __syncthreads();

        #pragma unroll
        for (int ni = 0; ni < 8; ni++) {
            int lc = wn * 64 + ni * 8 + tg * 2;
            int kk = lc >> 1;
            float2 bias = *(const float2*)(b1 + nc * 128 + lc);
            #pragma unroll
            for (int mi = 0; mi < 2; mi++) {
                int lr = wm * 32 + mi * 16 + g;
                float* d = acc1[mi][ni];
                Buf[lr * AS_S + kk] =
                    packbf(fmaxf(d[0] + bias.x, 0.f), fmaxf(d[1] + bias.y, 0.f));
                Buf[(lr + 8) * AS_S + kk] =
                    packbf(fmaxf(d[2] + bias.x, 0.f), fmaxf(d[3] + bias.y, 0.f));
            }
        }
        __syncthreads();

        const int m0 = wid * 16;
        #pragma unroll
        for (int ks = 0; ks < 8; ks++) {
            const int kk0 = ks * 8;
            uint32_t af[4];
            af[0] = Buf[(m0 + g    ) * AS_S + kk0 + tg    ];
            af[1] = Buf[(m0 + g + 8) * AS_S + kk0 + tg    ];
            af[2] = Buf[(m0 + g    ) * AS_S + kk0 + tg + 4];
            af[3] = Buf[(m0 + g + 8) * AS_S + kk0 + tg + 4];
            #pragma unroll
            for (int ni = 0; ni < 5; ni++) {
                uint32_t b0 = W2p[(kk0 + tg    ) * W2_S + ni * 8 + g];
                uint32_t b1f = W2p[(kk0 + tg + 4) * W2_S + ni * 8 + g];
                float* d = acc2[ni];
                asm volatile(
                    "mma.sync.aligned.m16n8k16.row.col.f32.bf16.bf16.f32 "
                    "{%0,%1,%2,%3}, {%4,%5,%6,%7}, {%8,%9}, {%0,%1,%2,%3};"
                    : "+f"(d[0]), "+f"(d[1]), "+f"(d[2]), "+f"(d[3])
                    : "r"(af[0]), "r"(af[1]), "r"(af[2]), "r"(af[3]),
                      "r"(b0), "r"(b1f));
            }
        }
        __syncthreads();
    }

    const int m0 = row0 + wid * 16;
    #pragma unroll
    for (int ni = 0; ni < 5; ni++) {
        int c = ni * 8 + tg * 2;
        float* d = acc2[ni];
        int r0 = m0 + g;
        if (r0 < N) *(float2*)(g_g2 + (size_t)r0 * NCLS + c) = make_float2(d[0], d[1]);
        int r1 = r0 + 8;
        if (r1 < N) *(float2*)(g_g2 + (size_t)r1 * NCLS + c) = make_float2(d[2], d[3]);
    }
}

// ---------------------------------------------------------------------------
// Fused: CSR-gather aggregation of g2 + bias + log_softmax -> out.
// One warp per node; lane l covers col l, lanes<8 also col 32+l. MLP-4 unroll.
__global__ void k_gout(const float* __restrict__ b2, float* __restrict__ out, int N) {
    int i = (int)((blockIdx.x * (unsigned)blockDim.x + threadIdx.x) >> 5);
    int l = threadIdx.x & 31;
    if (i >= N) return;
    int b  = g_rowptr[i];
    int e2 = g_rowptr[i + 1];
    float a0 = 0.f, a1 = 0.f;
    int j = b;
    for (; j + 4 <= e2; j += 4) {
        int s0 = g_csrc[j], s1 = g_csrc[j + 1], s2 = g_csrc[j + 2], s3 = g_csrc[j + 3];
        float w0 = g_dinv[s0], w1 = g_dinv[s1], w2 = g_dinv[s2], w3 = g_dinv[s3];
        const float* r0 = g_g2 + (size_t)s0 * NCLS;
        const float* r1 = g_g2 + (size_t)s1 * NCLS;
        const float* r2 = g_g2 + (size_t)s2 * NCLS;
        const float* r3 = g_g2 + (size_t)s3 * NCLS;
        a0 += w0 * r0[l] + w1 * r1[l] + w2 * r2[l] + w3 * r3[l];
        if (l < 8)
            a1 += w0 * r0[32 + l] + w1 * r1[32 + l] + w2 * r2[32 + l] + w3 * r3[32 + l];
    }
    for (; j < e2; j++) {
        int s = g_csrc[j];
        float w = g_dinv[s];
        const float* row = g_g2 + (size_t)s * NCLS;
        a0 += w * row[l];
        if (l < 8) a1 += w * row[32 + l];
    }
    float di = g_dinv[i];
    float d2 = di * di;
    const float* self = g_g2 + (size_t)i * NCLS;
    float v0 = di * a0 + d2 * self[l] + b2[l];
    float v1 = (l < 8) ? (di * a1 + d2 * self[32 + l] + b2[32 + l]) : -CUDART_INF_F;

    float m = fmaxf(v0, v1);
    #pragma unroll
    for (int o = 16; o; o >>= 1) m = fmaxf(m, __shfl_xor_sync(0xffffffffu, m, o));
    float s = expf(v0 - m) + ((l < 8) ? expf(v1 - m) : 0.f);
    #pragma unroll
    for (int o = 16; o; o >>= 1) s += __shfl_xor_sync(0xffffffffu, s, o);
    float lse = m + logf(s);
    out[(size_t)i * NCLS + l] = v0 - lse;
    if (l < 8) out[(size_t)i * NCLS + 32 + l] = v1 - lse;
}

// ---------------------------------------------------------------------------
extern "C" void kernel_launch(void* const* d_in, const int* in_sizes, int n_in,
                              void* d_out, int out_size) {
    const float* x  = (const float*)d_in[0];
    const int*   ei = (const int*)  d_in[1];
    const float* W1 = (const float*)d_in[2];
    const float* b1 = (const float*)d_in[3];
    const float* W2 = (const float*)d_in[4];
    const float* b2 = (const float*)d_in[5];
    float* out = (float*)d_out;

    int N = in_sizes[0] / IN_DIM;
    int E = in_sizes[1] / 2;
    const int* src = ei;
    const int* dst = ei + E;

    static int smem_set = 0;
    const int SMEM_FUSED = (128 * AS_S + 64 * BS_S + 64 * W2_S) * 4;  // 79,872 B
    if (!smem_set) {
        cudaFuncSetAttribute(k_fused, cudaFuncAttributeMaxDynamicSharedMemorySize,
                             SMEM_FUSED);
        smem_set = 1;
    }

    int NB = (N + SCAN_BLK - 1) / SCAN_BLK;   // 196 <= 256

    int* p_degi;
    cudaGetSymbolAddress((void**)&p_degi, g_degi);
    cudaMemsetAsync(p_degi, 0, (size_t)N * sizeof(int));

    k_deg <<<(E + 255) / 256, 256>>>(dst, E);

    // CSR build (+dinv folded into scan_a)
    k_scan_a<<<NB, 256>>>(N);
    k_scan_b<<<1, 256>>>(NB);
    k_scan_c<<<(N + 255) / 256, 256>>>(N, E);
    k_scatter<<<(E + 255) / 256, 256>>>(src, dst, E);

    // layer-1 aggregation (gather, atomic-free)
    {
        long threads = (long)N * 32;
        k_gax<<<(int)((threads + 255) / 256), 256>>>(x, N);
    }

    // fused GEMM1+relu+GEMM2
    k_fused<<<(N + 127) / 128, 256, SMEM_FUSED>>>(W1, b1, W2, N);

    // layer-2 aggregation + bias + log_softmax
    {
        long threads = (long)N * 32;
        k_gout<<<(int)((threads + 255) / 256), 256>>>(b2, out, N);
    }
}